// round 8
// baseline (speedup 1.0000x reference)
#include <cuda_runtime.h>
#include <cuda_bf16.h>
#include <math.h>
#include <stdint.h>

#define HW 65536

// ---------------------------------------------------------------------------
// Scratch (no allocations allowed)
// ---------------------------------------------------------------------------
__device__ float          g_f32[8ULL * 65536 * 32];    //  64 MB NHWC fp32 conv outputs
__device__ __nv_bfloat16  g_hi [8ULL * 65536 * 128];   // 128 MB NHWC bf16 hi
__device__ __nv_bfloat16  g_lo [8ULL * 65536 * 128];   // 128 MB NHWC bf16 lo
__device__ __align__(16) char g_wb[167424];            // B-hi padded row-major images
// w1hi@0 (18944, BSTR=592) ; w2hi@18944 (74240, BSTR=2320) ; w3hi@93184 (74240)
__device__ __align__(16) char g_wfrag[165888];         // B-lo in mma-fragment layout
// w1frag@0 (18*1024) ; w2frag@18432 (72*1024) ; w3frag@92160 (72*1024)

// ---------------------------------------------------------------------------
__device__ __forceinline__ uint32_t smem_u32(const void* p) {
    uint32_t a;
    asm("{ .reg .u64 t; cvta.to.shared.u64 t, %1; cvt.u32.u64 %0, t; }" : "=r"(a) : "l"(p));
    return a;
}
__device__ __forceinline__ void ldm4(uint32_t* r, uint32_t a) {
    asm volatile("ldmatrix.sync.aligned.m8n8.x4.shared.b16 {%0,%1,%2,%3}, [%4];"
                 : "=r"(r[0]), "=r"(r[1]), "=r"(r[2]), "=r"(r[3]) : "r"(a));
}
__device__ __forceinline__ void mma16816(float* c, const uint32_t* a, uint32_t b0, uint32_t b1) {
    asm volatile("mma.sync.aligned.m16n8k16.row.col.f32.bf16.bf16.f32 "
        "{%0,%1,%2,%3}, {%4,%5,%6,%7}, {%8,%9}, {%0,%1,%2,%3};"
        : "+f"(c[0]), "+f"(c[1]), "+f"(c[2]), "+f"(c[3])
        : "r"(a[0]), "r"(a[1]), "r"(a[2]), "r"(a[3]), "r"(b0), "r"(b1));
}
__device__ __forceinline__ void cp16(uint32_t saddr, const void* gaddr, int sz) {
    asm volatile("cp.async.cg.shared.global [%0], [%1], 16, %2;"
                 :: "r"(saddr), "l"(gaddr), "r"(sz));
}
__device__ __forceinline__ void cp_commit() { asm volatile("cp.async.commit_group;"); }
__device__ __forceinline__ void cp_wait0()  { asm volatile("cp.async.wait_group 0;"); }

// ---------------------------------------------------------------------------
// Weight prep (hi): fp32 [32][CIN][3][3] -> bf16 hi padded row-major B image.
// ---------------------------------------------------------------------------
__global__ void prep_w(const float* __restrict__ w, char* __restrict__ bhi, int CIN)
{
    int K = 9 * CIN, KP = K + 8, BSTR = K * 2 + 16;
    int idx = blockIdx.x * 256 + threadIdx.x;
    if (idx >= 32 * KP) return;
    int n = idx / KP, k = idx - n * KP;
    float v = 0.f;
    if (k < K) {
        int dyi = k / (3 * CIN);
        int r   = k - dyi * 3 * CIN;
        int dxi = r / CIN;
        int c   = r - dxi * CIN;
        v = w[(n * CIN + c) * 9 + dyi * 3 + dxi];
    }
    *(__nv_bfloat16*)(bhi + n * BSTR + k * 2) = __float2bfloat16(v);
}

// ---------------------------------------------------------------------------
// Weight prep (lo): B-lo directly in mma.m16n8k16 B-fragment layout.
// combo cid = (dy*3+dx)*(CIN/16)+kc ; per combo 32 lanes x 8 u32 = 1KB.
// lane l, slot j: n = (l>>2) + ((j>>1)&1)*8 + ((j>>2)&1)*16 ;
//                 k = kc*16 + (l&3)*2 + (j&1)*8  (pair k, k+1)
// ---------------------------------------------------------------------------
__global__ void prep_wfrag(const float* __restrict__ w, char* __restrict__ dst, int CIN)
{
    int kc16 = CIN / 16;
    int total = 9 * kc16 * 256;
    int idx = blockIdx.x * 256 + threadIdx.x;
    if (idx >= total) return;
    int cid = idx >> 8;
    int r   = idx & 255;
    int lane = r >> 3, j = r & 7;
    int dydx = cid / kc16, kc = cid - dydx * kc16;
    int dy = dydx / 3, dx = dydx - dy * 3;
    int n = (lane >> 2) + ((j >> 1) & 1) * 8 + ((j >> 2) & 1) * 16;
    int c0 = kc * 16 + (lane & 3) * 2 + (j & 1) * 8;

    float v0 = w[(n * CIN + c0) * 9 + dy * 3 + dx];
    float v1 = w[(n * CIN + c0 + 1) * 9 + dy * 3 + dx];
    float h0 = __bfloat162float(__float2bfloat16(v0));
    float h1 = __bfloat162float(__float2bfloat16(v1));
    uint16_t l0 = __bfloat16_as_ushort(__float2bfloat16(v0 - h0));
    uint16_t l1 = __bfloat16_as_ushort(__float2bfloat16(v1 - h1));
    *(uint32_t*)(dst + cid * 1024 + lane * 32 + j * 4) = (uint32_t)l0 | ((uint32_t)l1 << 16);
}

// ---------------------------------------------------------------------------
// x (NCHW fp32) -> NHWC bf16 hi/lo (32 ch)
// ---------------------------------------------------------------------------
__global__ __launch_bounds__(256)
void transpose_x(const float* __restrict__ x, __nv_bfloat16* __restrict__ ohi,
                 __nv_bfloat16* __restrict__ olo)
{
    __shared__ float t[32][33];
    int b = blockIdx.y;
    int p0 = blockIdx.x * 32;
    int lane = threadIdx.x & 31, grp = threadIdx.x >> 5;
#pragma unroll
    for (int i = 0; i < 4; i++) {
        int c = grp + i * 8;
        t[c][lane] = x[((size_t)b * 32 + c) * HW + p0 + lane];
    }
    __syncthreads();
#pragma unroll
    for (int i = 0; i < 4; i++) {
        int p = grp + i * 8;
        float v = t[lane][p];
        __nv_bfloat16 hi = __float2bfloat16(v);
        __nv_bfloat16 lo = __float2bfloat16(v - __bfloat162float(hi));
        size_t o = ((size_t)b * HW + p0 + p) * 32 + lane;
        ohi[o] = hi; olo[o] = lo;
    }
}

// ---------------------------------------------------------------------------
// HMMA implicit-GEMM 3x3 conv, 4 output rows/CTA, double-buffered A pipeline.
// smem: [Bhi][A0hi][A0lo][A1hi][A1lo].  B-hi via ldmatrix, B-lo frags via LDG.
// Split-3: acc += Ahi*Bhi + Alo*Bhi + Ahi*Blo.
// ---------------------------------------------------------------------------
template<int CIN, bool FUSE>
__global__ __launch_bounds__(256, 1)
void conv_mma(const __nv_bfloat16* __restrict__ ahi, const __nv_bfloat16* __restrict__ alo,
              const char* __restrict__ wb, const char* __restrict__ wfrag,
              const float* __restrict__ wout, float* __restrict__ out)
{
    constexpr int K     = 9 * CIN;
    constexpr int ASTR  = CIN * 2 + 16;        // A row stride (bytes)
    constexpr int BSTR  = K * 2 + 16;          // B row stride (bytes)
    constexpr int BBYT  = 32 * BSTR;           // B-hi image
    constexpr int V4    = CIN / 8;             // uint4 per pixel-row
    constexpr int ABYT  = 130 * ASTR;          // one input row, one split
    constexpr int KC16  = CIN / 16;

    extern __shared__ __align__(16) char smem[];
    const int tid  = threadIdx.x;
    const int lane = tid & 31;
    const int wid  = tid >> 5;
    const int w0   = blockIdx.x << 7;
    const int h0   = blockIdx.y << 2;
    const int b    = blockIdx.z;

    const uint32_t s0 = smem_u32(smem);

    // B-hi copy (async; waited together with A row 0)
    {
        const int n4 = BBYT / 16;
        for (int i = tid; i < n4; i += 256)
            cp16(s0 + i * 16, wb + i * 16, 16);
        cp_commit();
    }

    // prefetch A input row for stage 0 into buffer 0
    auto prefetch = [&](int s) {
        const int ir = h0 - 1 + s;
        const uint32_t abase = s0 + BBYT + (uint32_t)(s & 1) * 2 * ABYT;
        if ((unsigned)ir < 256u) {
            const size_t rowbase = ((size_t)b * HW + (size_t)ir * 256);
            for (int i = tid; i < 130 * V4; i += 256) {
                int px = i / V4, v = i - px * V4;
                int w  = w0 - 1 + px;
                int ok = ((unsigned)w < 256u);
                int wc = ok ? w : 0;
                uint32_t d = (uint32_t)(px * ASTR + v * 16);
                cp16(abase + d,        (const char*)(ahi + (rowbase + wc) * CIN) + v * 16, ok ? 16 : 0);
                cp16(abase + ABYT + d, (const char*)(alo + (rowbase + wc) * CIN) + v * 16, ok ? 16 : 0);
            }
        }
        cp_commit();
    };
    prefetch(0);

    const int m0 = wid * 16;
    const uint32_t aRowOff = (uint32_t)(lane & 15) * ASTR + ((lane & 16) ? 16u : 0u);
    const uint32_t bLM = (uint32_t)((lane & 7) + ((lane & 16) ? 8 : 0)) * BSTR
                       + (uint32_t)((lane >> 3) & 1) * 16;
    const char* fragBase = wfrag + lane * 32;

    float acc[4][16];
#pragma unroll
    for (int r = 0; r < 4; r++)
#pragma unroll
        for (int i = 0; i < 16; i++) acc[r][i] = 0.f;

    for (int s = 0; s < 6; s++) {
        const int ir = h0 - 1 + s;
        cp_wait0();
        __syncthreads();
        if (s < 5) prefetch(s + 1);
        if ((unsigned)ir >= 256u) continue;

        const uint32_t abuf = s0 + BBYT + (uint32_t)(s & 1) * 2 * ABYT;
        const uint32_t sAhi = abuf, sAlo = abuf + ABYT;

#pragma unroll
        for (int r = 0; r < 4; r++) {
            const int dy = s - r;
            if (dy < 0 || dy > 2) continue;
#pragma unroll
            for (int dx = 0; dx < 3; dx++) {
#pragma unroll
                for (int kc = 0; kc < KC16; kc++) {
                    uint32_t ah[4], al[4];
                    const uint32_t abase = (uint32_t)(m0 + dx) * ASTR + kc * 32 + aRowOff;
                    ldm4(ah, sAhi + abase);
                    ldm4(al, sAlo + abase);
                    const uint32_t kb = (uint32_t)(dy * 3 * CIN + dx * CIN + kc * 16) * 2;
                    uint32_t bh[4], bh2[4];
                    ldm4(bh,  s0 + bLM + kb);                 // n0-15
                    ldm4(bh2, s0 + bLM + kb + 16 * BSTR);     // n16-31
                    const int cid = (dy * 3 + dx) * KC16 + kc;
                    const uint4* fp = (const uint4*)(fragBase + cid * 1024);
                    uint4 f0 = fp[0], f1 = fp[1];             // B-lo frags (L2)
                    float* a0 = acc[r];
                    mma16816(a0 + 0,  ah, bh[0],  bh[1]);
                    mma16816(a0 + 4,  ah, bh[2],  bh[3]);
                    mma16816(a0 + 8,  ah, bh2[0], bh2[1]);
                    mma16816(a0 + 12, ah, bh2[2], bh2[3]);
                    mma16816(a0 + 0,  al, bh[0],  bh[1]);
                    mma16816(a0 + 4,  al, bh[2],  bh[3]);
                    mma16816(a0 + 8,  al, bh2[0], bh2[1]);
                    mma16816(a0 + 12, al, bh2[2], bh2[3]);
                    mma16816(a0 + 0,  ah, f0.x, f0.y);
                    mma16816(a0 + 4,  ah, f0.z, f0.w);
                    mma16816(a0 + 8,  ah, f1.x, f1.y);
                    mma16816(a0 + 12, ah, f1.z, f1.w);
                }
            }
        }
    }

    // epilogue (4 rows)
    const int prow = m0 + (lane >> 2);
#pragma unroll
    for (int r = 0; r < 4; r++) {
        const int h = h0 + r;
        if (!FUSE) {
            float* ob = out + ((size_t)b * HW + (size_t)h * 256 + w0) * 32;
#pragma unroll
            for (int nt = 0; nt < 4; nt++) {
                int ch = nt * 8 + (lane & 3) * 2;
                *(float2*)(ob + (size_t)prow * 32 + ch)       = make_float2(acc[r][nt * 4 + 0], acc[r][nt * 4 + 1]);
                *(float2*)(ob + (size_t)(prow + 8) * 32 + ch) = make_float2(acc[r][nt * 4 + 2], acc[r][nt * 4 + 3]);
            }
        } else {
            float s0v = 0.f, s1v = 0.f;
#pragma unroll
            for (int nt = 0; nt < 4; nt++) {
                int ch = nt * 8 + (lane & 3) * 2;
                float wa = __ldg(&wout[ch]), wb2 = __ldg(&wout[ch + 1]);
                s0v += fmaxf(acc[r][nt * 4 + 0], 0.f) * wa + fmaxf(acc[r][nt * 4 + 1], 0.f) * wb2;
                s1v += fmaxf(acc[r][nt * 4 + 2], 0.f) * wa + fmaxf(acc[r][nt * 4 + 3], 0.f) * wb2;
            }
            s0v += __shfl_xor_sync(0xffffffffu, s0v, 1);
            s0v += __shfl_xor_sync(0xffffffffu, s0v, 2);
            s1v += __shfl_xor_sync(0xffffffffu, s1v, 1);
            s1v += __shfl_xor_sync(0xffffffffu, s1v, 2);
            if ((lane & 3) == 0) {
                size_t ob = (size_t)b * HW + (size_t)h * 256 + w0;
                out[ob + prow]     = 1.0f / (1.0f + expf(-s0v));
                out[ob + prow + 8] = 1.0f / (1.0f + expf(-s1v));
            }
        }
    }
}

// ---------------------------------------------------------------------------
// IRNN: all 4 directional scans in ONE kernel (blockIdx.y = direction).
// ---------------------------------------------------------------------------
template<bool REV>
__device__ __forceinline__
void scan_h_body(const float* __restrict__ in, __nv_bfloat16* __restrict__ ohi,
                 __nv_bfloat16* __restrict__ olo, float wc, float bc, int c, int ch_off)
{
    int t = blockIdx.x * 256 + threadIdx.x;      // over B*W*C = 65536
    int w = (t >> 5) & 255, b = t >> 13;
    const float* ip = in + (size_t)b * HW * 32 + (size_t)w * 32 + c;
    size_t ob = (size_t)b * HW * 128 + (size_t)w * 128 + ch_off + c;

    float hst = REV ? ip[(size_t)255 * 8192] : ip[0];
    {
        size_t o = ob + (size_t)(REV ? 255 : 0) * 32768;
        __nv_bfloat16 hi = __float2bfloat16(hst);
        ohi[o] = hi; olo[o] = __float2bfloat16(hst - __bfloat162float(hi));
    }
#pragma unroll 8
    for (int i = 1; i < 256; i++) {
        int y = REV ? (255 - i) : i;
        hst = fmaxf(wc * hst + bc + ip[(size_t)y * 8192], 0.f);
        size_t o = ob + (size_t)y * 32768;
        __nv_bfloat16 hi = __float2bfloat16(hst);
        ohi[o] = hi; olo[o] = __float2bfloat16(hst - __bfloat162float(hi));
    }
}

template<bool REV>
__device__ __forceinline__
void scan_w_body(const float* __restrict__ in, __nv_bfloat16* __restrict__ ohi,
                 __nv_bfloat16* __restrict__ olo, float wc, float bc, int c, int ch_off)
{
    int t = blockIdx.x * 256 + threadIdx.x;      // over B*H*C = 65536
    int h = (t >> 5) & 255, b = t >> 13;
    const float* ip = in + (size_t)b * HW * 32 + (size_t)h * 8192 + c;
    size_t ob = (size_t)b * HW * 128 + (size_t)h * 32768 + ch_off + c;

    float hst = REV ? ip[255 * 32] : ip[0];
    {
        size_t o = ob + (size_t)(REV ? 255 : 0) * 128;
        __nv_bfloat16 hi = __float2bfloat16(hst);
        ohi[o] = hi; olo[o] = __float2bfloat16(hst - __bfloat162float(hi));
    }
#pragma unroll 8
    for (int i = 1; i < 256; i++) {
        int w = REV ? (255 - i) : i;
        hst = fmaxf(wc * hst + bc + ip[w * 32], 0.f);
        size_t o = ob + (size_t)w * 128;
        __nv_bfloat16 hi = __float2bfloat16(hst);
        ohi[o] = hi; olo[o] = __float2bfloat16(hst - __bfloat162float(hi));
    }
}

__global__ __launch_bounds__(256)
void scan_all(const float* __restrict__ in, __nv_bfloat16* __restrict__ ohi,
              __nv_bfloat16* __restrict__ olo, const float* __restrict__ ws,
              const float* __restrict__ bs)
{
    const int d = blockIdx.y;
    const int c = threadIdx.x & 31;
    const float wc = ws[d * 32 + c], bc = bs[d * 32 + c];
    if      (d == 0) scan_h_body<true >(in, ohi, olo, wc, bc, c, 0);    // up
    else if (d == 1) scan_w_body<false>(in, ohi, olo, wc, bc, c, 32);   // right
    else if (d == 2) scan_h_body<false>(in, ohi, olo, wc, bc, c, 64);   // down
    else             scan_w_body<true >(in, ohi, olo, wc, bc, c, 96);   // left
}

// ---------------------------------------------------------------------------
extern "C" void kernel_launch(void* const* d_in, const int* in_sizes, int n_in,
                              void* d_out, int out_size)
{
    const float* x   = (const float*)d_in[0];
    const float* w1  = (const float*)d_in[1];
    const float* w2  = (const float*)d_in[2];
    const float* w3  = (const float*)d_in[3];
    const float* wo  = (const float*)d_in[4];
    const float* i1w = (const float*)d_in[5];
    const float* i1b = (const float*)d_in[6];
    const float* i2w = (const float*)d_in[7];
    const float* i2b = (const float*)d_in[8];
    float* outp = (float*)d_out;

    float* gf;  __nv_bfloat16 *ghi, *glo;  char *gwb, *gwf;
    cudaGetSymbolAddress((void**)&gf,  g_f32);
    cudaGetSymbolAddress((void**)&ghi, g_hi);
    cudaGetSymbolAddress((void**)&glo, g_lo);
    cudaGetSymbolAddress((void**)&gwb, g_wb);
    cudaGetSymbolAddress((void**)&gwf, g_wfrag);

    // smem: conv1 = 18944 + 4*10400 = 60544 ; conv2/3 = 74240 + 4*35360 = 215680
    cudaFuncSetAttribute(conv_mma<32,  false>, cudaFuncAttributeMaxDynamicSharedMemorySize, 60544);
    cudaFuncSetAttribute(conv_mma<128, false>, cudaFuncAttributeMaxDynamicSharedMemorySize, 215680);
    cudaFuncSetAttribute(conv_mma<128, true >, cudaFuncAttributeMaxDynamicSharedMemorySize, 215680);

    // prep B-hi images + B-lo fragment images
    prep_w<<<(32 * 296  + 255) / 256, 256>>>(w1, gwb + 0,     32);
    prep_w<<<(32 * 1160 + 255) / 256, 256>>>(w2, gwb + 18944, 128);
    prep_w<<<(32 * 1160 + 255) / 256, 256>>>(w3, gwb + 93184, 128);
    prep_wfrag<<<(18 * 256 + 255) / 256, 256>>>(w1, gwf + 0,     32);
    prep_wfrag<<<(72 * 256 + 255) / 256, 256>>>(w2, gwf + 18432, 128);
    prep_wfrag<<<(72 * 256 + 255) / 256, 256>>>(w3, gwf + 92160, 128);

    // x -> NHWC bf16 split (32 ch)
    transpose_x<<<dim3(2048, 8), 256>>>(x, ghi, glo);

    dim3 cg(2, 64, 8);   // 4 output rows per CTA
    conv_mma<32, false><<<cg, 256, 60544>>>(ghi, glo, gwb + 0, gwf + 0, nullptr, gf);

    scan_all<<<dim3(256, 4), 256>>>(gf, ghi, glo, i1w, i1b);

    conv_mma<128, false><<<cg, 256, 215680>>>(ghi, glo, gwb + 18944, gwf + 18432, nullptr, gf);

    scan_all<<<dim3(256, 4), 256>>>(gf, ghi, glo, i2w, i2b);

    conv_mma<128, true><<<cg, 256, 215680>>>(ghi, glo, gwb + 93184, gwf + 92160, wo, outp);
}